// round 17
// baseline (speedup 1.0000x reference)
#include <cuda_runtime.h>
#include <cuda_fp16.h>
#include <cstdint>

// Problem constants (fixed by the reference setup)
#define BB 2
#define NN 2048
#define DD 1024
#define HH 16
#define HD 64
#define INNER 1024
#define HALF 128
#define ROWS (BB*NN)      // 4096
#define KDIM 1024

// ---------------- scratch (device globals; allocation-free rule) -------------
__device__ float g_dummy[32];
__device__ __half g_xh[ROWS * KDIM];
__device__ __half g_ah[ROWS * KDIM];
__device__ __half g_whi[4 * KDIM * KDIM];
// row-major fp16 q/k/v: [b*NN+n][1024]
__device__ __half g_qh[ROWS * INNER];
__device__ __half g_kh[ROWS * INNER];
__device__ __half g_vh[ROWS * INNER];

// ================= baseline-ISA helpers ======================================
__device__ __forceinline__ uint32_t smem_u32(const void* p) {
    uint32_t a;
    asm("{ .reg .u64 t; cvta.to.shared.u64 t, %1; cvt.u32.u64 %0, t; }"
        : "=r"(a) : "l"(p));
    return a;
}
__device__ __forceinline__ void cp_async16(uint32_t saddr, const void* gaddr) {
    asm volatile("cp.async.cg.shared.global [%0], [%1], 16;"
                 :: "r"(saddr), "l"(gaddr));
}
__device__ __forceinline__ void cp_commit() {
    asm volatile("cp.async.commit_group;");
}
__device__ __forceinline__ void ldsm4(uint32_t* r, uint32_t addr) {
    asm volatile("ldmatrix.sync.aligned.m8n8.x4.shared.b16 {%0,%1,%2,%3}, [%4];"
        : "=r"(r[0]), "=r"(r[1]), "=r"(r[2]), "=r"(r[3]) : "r"(addr));
}
__device__ __forceinline__ void ldsm4t(uint32_t* r, uint32_t addr) {
    asm volatile("ldmatrix.sync.aligned.m8n8.x4.trans.shared.b16 {%0,%1,%2,%3}, [%4];"
        : "=r"(r[0]), "=r"(r[1]), "=r"(r[2]), "=r"(r[3]) : "r"(addr));
}
__device__ __forceinline__ void mma16816(float* d, const uint32_t* a,
                                         uint32_t b0, uint32_t b1) {
    asm volatile("mma.sync.aligned.m16n8k16.row.col.f32.f16.f16.f32 "
        "{%0,%1,%2,%3}, {%4,%5,%6,%7}, {%8,%9}, {%0,%1,%2,%3};"
        : "+f"(d[0]), "+f"(d[1]), "+f"(d[2]), "+f"(d[3])
        : "r"(a[0]), "r"(a[1]), "r"(a[2]), "r"(a[3]), "r"(b0), "r"(b1));
}
__device__ __forceinline__ uint32_t packh2(float x, float y) {
    __half2 t = __floats2half2_rn(x, y);
    return *(uint32_t*)&t;
}
__device__ __forceinline__ uint32_t swz(int row, int c) {
    return (uint32_t)(row * 128 + (((c ^ (row & 7)) & 7) << 4));
}

// ================= merged conversion kernel ==================================
// m = i>>18: 0..3 -> W matrix m -> whi; 4..7 -> x chunk (m-4) -> xh.
#define N4W (KDIM*KDIM/4)
__global__ void convert_all(const float* __restrict__ x,
                            const float* __restrict__ Wq, const float* __restrict__ Wk,
                            const float* __restrict__ Wv, const float* __restrict__ Wo,
                            __half* __restrict__ whi, __half* __restrict__ xh)
{
    int i = blockIdx.x * blockDim.x + threadIdx.x;   // 0 .. 8*N4W-1
    int m = i >> 18;
    int il = i & (N4W - 1);
    const float* src;
    __half* dst;
    size_t o;
    if (m < 4) {
        src = (m == 0) ? Wq : (m == 1) ? Wk : (m == 2) ? Wv : Wo;
        dst = whi;  o = (size_t)m * N4W + il;
    } else {
        src = x + (size_t)(m - 4) * N4W * 4;
        dst = xh;   o = (size_t)(m - 4) * N4W + il;
    }
    float4 v = ((const float4*)src)[il];
    ((__half2*)dst)[2*o]   = __floats2half2_rn(v.x, v.y);
    ((__half2*)dst)[2*o+1] = __floats2half2_rn(v.z, v.w);
}

__global__ void dummy_k(float* p) { if (threadIdx.x == 0) p[0] = 0.f; }

// ================= single-product fp16 HMMA GEMM, 4 stages ===================
// CTA tile 128(M) x 128(N), BK=32, 256 threads (8 warps 2x4, warp 64x32).
#define NSTAGE 4
#define GSTAGE 16384
#define GSMEM (NSTAGE*GSTAGE)   // 65536
#define NSTEP (KDIM/32)         // 32

__global__ __launch_bounds__(256, 2)
void gemm_f16(const __half* __restrict__ Ah,
              const __half* __restrict__ Wh,
              const float* __restrict__ bias0, const float* __restrict__ bias1,
              const float* __restrict__ bias2,
              float* __restrict__ Cf,
              __half* __restrict__ H0, __half* __restrict__ H1,
              __half* __restrict__ H2,
              int fp16_out)
{
    extern __shared__ __align__(128) char sm[];
    const uint32_t smb = smem_u32(sm);
    const int tid  = threadIdx.x;
    const int lane = tid & 31, wid = tid >> 5;
    const int bx = blockIdx.x, by = blockIdx.y;
    const int m = bx >> 3, bxl = bx & 7;
    const int warp_m = wid >> 2, warp_n = wid & 3;

    const __half* Bhi = Wh + (size_t)m * KDIM * KDIM;
    const float* bias = (m == 0) ? bias0 : (m == 1) ? bias1 : bias2;

    const int ar = tid >> 2, akc = tid & 3;
    const uint32_t aoff0 = (uint32_t)ar * 64 + ((akc ^ ((ar >> 1) & 3)) << 4);
    const uint32_t aoff1 = aoff0 + 4096;
    const __half* gA0 = Ah + (size_t)(by * 128 + ar) * KDIM + akc * 8;
    const __half* gA1 = gA0 + (size_t)64 * KDIM;

    const int bk = tid >> 4, bnc = tid & 15;
    const uint32_t boff = (uint32_t)bk * 256 + ((bnc ^ (bk & 7)) << 4);
    const __half* gBh = Bhi + (size_t)bk * KDIM + bxl * 128 + bnc * 8;

    uint32_t a_addr[4][2], b_addr[2][2];
    #pragma unroll
    for (int mi = 0; mi < 4; mi++)
        #pragma unroll
        for (int kk = 0; kk < 2; kk++) {
            int row = warp_m * 64 + mi * 16 + (lane & 15);
            int kc  = kk * 2 + (lane >> 4);
            a_addr[mi][kk] = smb + (uint32_t)row * 64 + ((kc ^ ((row >> 1) & 3)) << 4);
        }
    #pragma unroll
    for (int kk = 0; kk < 2; kk++)
        #pragma unroll
        for (int nj = 0; nj < 2; nj++) {
            int k  = kk * 16 + (lane & 15);
            int nc = warp_n * 4 + nj * 2 + (lane >> 4);
            b_addr[kk][nj] = smb + 8192 + (uint32_t)k * 256 + ((nc ^ (k & 7)) << 4);
        }

    float acc[4][4][4];
    #pragma unroll
    for (int i = 0; i < 4; i++)
        #pragma unroll
        for (int j = 0; j < 4; j++)
            #pragma unroll
            for (int r = 0; r < 4; r++) acc[i][j][r] = 0.f;

    #pragma unroll
    for (int p = 0; p < NSTAGE - 1; p++) {
        const int k0 = p * 32;
        uint32_t st = smb + p * GSTAGE;
        cp_async16(st + aoff0,               gA0 + k0);
        cp_async16(st + aoff1,               gA1 + k0);
        cp_async16(st + 8192 + boff,         gBh + (size_t)k0 * KDIM);
        cp_async16(st + 8192 + boff + 4096,  gBh + (size_t)(k0 + 16) * KDIM);
        cp_commit();
    }

    int slot = 0, pslot = NSTAGE - 1;
    for (int s = 0; s < NSTEP; s++) {
        asm volatile("cp.async.wait_group %0;" :: "n"(NSTAGE - 2));
        __syncthreads();

        if (s + NSTAGE - 1 < NSTEP) {
            const int k0 = (s + NSTAGE - 1) * 32;
            uint32_t st = smb + (uint32_t)pslot * GSTAGE;
            cp_async16(st + aoff0,               gA0 + k0);
            cp_async16(st + aoff1,               gA1 + k0);
            cp_async16(st + 8192 + boff,         gBh + (size_t)k0 * KDIM);
            cp_async16(st + 8192 + boff + 4096,  gBh + (size_t)(k0 + 16) * KDIM);
        }
        cp_commit();

        const uint32_t so = (uint32_t)slot * GSTAGE;
        #pragma unroll
        for (int kk = 0; kk < 2; kk++) {
            uint32_t ah[4][4], bh[2][4];
            ldsm4 (ah[0], a_addr[0][kk] + so);
            ldsm4 (ah[1], a_addr[1][kk] + so);
            ldsm4 (ah[2], a_addr[2][kk] + so);
            ldsm4 (ah[3], a_addr[3][kk] + so);
            ldsm4t(bh[0], b_addr[kk][0] + so);
            ldsm4t(bh[1], b_addr[kk][1] + so);
            #pragma unroll
            for (int mi = 0; mi < 4; mi++)
                #pragma unroll
                for (int nj = 0; nj < 2; nj++) {
                    mma16816(acc[mi][2*nj],   ah[mi], bh[nj][0], bh[nj][1]);
                    mma16816(acc[mi][2*nj+1], ah[mi], bh[nj][2], bh[nj][3]);
                }
        }
        slot  = (slot  + 1 == NSTAGE) ? 0 : slot  + 1;
        pslot = (pslot + 1 == NSTAGE) ? 0 : pslot + 1;
    }

    // ---- epilogue ----
    const int cbase = bxl * 128 + warp_n * 32;
    if (fp16_out) {
        __half* H = (m == 0) ? H0 : (m == 1) ? H1 : H2;
        const float sc = (m == 0) ? 0.125f : 1.0f;
        #pragma unroll
        for (int mi = 0; mi < 4; mi++) {
            const int r0 = by * 128 + warp_m * 64 + mi * 16 + (lane >> 2);
            #pragma unroll
            for (int t = 0; t < 4; t++) {
                const int col = cbase + t * 8 + (lane & 3) * 2;
                float2 bv = *(const float2*)&bias[col];
                float v0 = (acc[mi][t][0] + bv.x) * sc;
                float v1 = (acc[mi][t][1] + bv.y) * sc;
                float v2 = (acc[mi][t][2] + bv.x) * sc;
                float v3 = (acc[mi][t][3] + bv.y) * sc;
                *(uint32_t*)&H[(size_t)r0 * INNER + col]       = packh2(v0, v1);
                *(uint32_t*)&H[(size_t)(r0 + 8) * INNER + col] = packh2(v2, v3);
            }
        }
    } else {
        #pragma unroll
        for (int mi = 0; mi < 4; mi++) {
            const int r0 = by * 128 + warp_m * 64 + mi * 16 + (lane >> 2);
            #pragma unroll
            for (int t = 0; t < 4; t++) {
                const int col = cbase + t * 8 + (lane & 3) * 2;
                float2 bv = *(const float2*)&bias[col];
                float2 o0 = make_float2(acc[mi][t][0] + bv.x, acc[mi][t][1] + bv.y);
                float2 o1 = make_float2(acc[mi][t][2] + bv.x, acc[mi][t][3] + bv.y);
                *(float2*)&Cf[(size_t)r0 * INNER + col]       = o0;
                *(float2*)&Cf[(size_t)(r0 + 8) * INNER + col] = o1;
            }
        }
    }
}

// ====== tensor-core windowed attention: row-major fp16, fused head-0 RoPE ====
// smem: Q 16KB, Kh 24KB, Vh 24KB = 64KB -> 2 CTAs/SM.
#define ASMEM 65536
__global__ __launch_bounds__(256, 2)
void attn_mma(const __half* __restrict__ qh_, const __half* __restrict__ kh_,
              const __half* __restrict__ vh_, const float* __restrict__ freqs,
              __half* __restrict__ oah)
{
    extern __shared__ __align__(128) char sm[];
    const uint32_t smb = smem_u32(sm);
    enum { SQ = 0, SKH = 16384, SVH = 40960 };

    const int tid = threadIdx.x, w = tid >> 5, lane = tid & 31;
    const int q0 = blockIdx.x * 128;
    const int bh = blockIdx.y;
    const int b = bh >> 4, h = bh & 15;
    const int hcol = h * HD;

    // ---- Q load (RoPE for h==0) ----
    #pragma unroll
    for (int it = 0; it < 4; it++) {
        int idx = tid + it * 256; int row = idx >> 3, c = idx & 7;
        uint32_t off = swz(row, c);
        size_t g = (size_t)(b * NN + q0 + row) * INNER + hcol + c * 8;
        uint4 v = *(const uint4*)(qh_ + g);
        if (h == 0) {
            int n = q0 + row;
            __half2* ph = (__half2*)&v;
            const float2* fp = (const float2*)&freqs[n * HD + c * 8];
            #pragma unroll
            for (int p = 0; p < 4; p++) {
                float2 f = fp[p];
                float x0 = __half2float(ph[p].x), y0 = __half2float(ph[p].y);
                *(uint32_t*)&ph[p] = packh2(x0 * cosf(f.x) - y0 * sinf(f.x),
                                            y0 * cosf(f.y) + x0 * sinf(f.y));
            }
        }
        *(uint4*)(sm + SQ + off) = v;
    }
    __syncthreads();

    uint32_t qf[4][4];
    {
        int qrow = 16 * w + (lane & 15);
        #pragma unroll
        for (int kk = 0; kk < 4; kk++) {
            uint32_t off = swz(qrow, 2 * kk + (lane >> 4));
            ldsm4(qf[kk], smb + SQ + off);
        }
    }

    float oacc[8][4];
    #pragma unroll
    for (int t = 0; t < 8; t++)
        #pragma unroll
        for (int r = 0; r < 4; r++) oacc[t][r] = 0.f;
    float lsum0 = 0.f, lsum1 = 0.f;

    const int i0 = q0 + 16 * w + (lane >> 2);
    const int kroff = ((lane >> 4) << 3) + (lane & 7);
    const int kchoff = (lane >> 3) & 1;
    const int vroff = lane & 15;
    const int vchoff = lane >> 4;
    const uint4 z4 = make_uint4(0, 0, 0, 0);

    #pragma unroll 1
    for (int cc = 0; cc < 2; cc++) {
        // ---- K/V chunk load (K RoPE for h==0) ----
        #pragma unroll 1
        for (int it = 0; it < 6; it++) {
            int idx = tid + it * 256; int row = idx >> 3, c = idx & 7;
            int j = q0 - 128 + 192 * cc + row;
            uint32_t off = swz(row, c);
            if (j >= 0 && j < NN) {
                size_t g = (size_t)(b * NN + j) * INNER + hcol + c * 8;
                uint4 kv = *(const uint4*)(kh_ + g);
                if (h == 0) {
                    __half2* ph = (__half2*)&kv;
                    const float2* fp = (const float2*)&freqs[j * HD + c * 8];
                    #pragma unroll
                    for (int p = 0; p < 4; p++) {
                        float2 f = fp[p];
                        float x0 = __half2float(ph[p].x), y0 = __half2float(ph[p].y);
                        *(uint32_t*)&ph[p] = packh2(x0 * cosf(f.x) - y0 * sinf(f.x),
                                                    y0 * cosf(f.y) + x0 * sinf(f.y));
                    }
                }
                *(uint4*)(sm + SKH + off) = kv;
                *(uint4*)(sm + SVH + off) = *(const uint4*)(vh_ + g);
            } else {
                *(uint4*)(sm + SKH + off) = z4;
                *(uint4*)(sm + SVH + off) = z4;
            }
        }
        __syncthreads();

        int gmin = w - 12 * cc;                      if (gmin < 0) gmin = 0;
        int gmax = (16 * w + 271 - 192 * cc) >> 4;   if (gmax > 11) gmax = 11;
        const int jbase = q0 - 128 + 192 * cc;

        #pragma unroll 1
        for (int g = gmin; g <= gmax; g++) {
            float s[8];
            #pragma unroll
            for (int e = 0; e < 8; e++) s[e] = 0.f;
            const int krow = 16 * g + kroff;
            #pragma unroll
            for (int kk = 0; kk < 4; kk++) {
                uint32_t off = swz(krow, 2 * kk + kchoff);
                uint32_t kb[4];
                ldsm4(kb, smb + SKH + off);
                mma16816(s + 0, qf[kk], kb[0], kb[1]);
                mma16816(s + 4, qf[kk], kb[2], kb[3]);
            }
            float p[8];
            #pragma unroll
            for (int e = 0; e < 8; e++) {
                int col = 16 * g + 8 * (e >> 2) + 2 * (lane & 3) + (e & 1);
                int j = jbase + col;
                int i = i0 + ((e & 2) ? 8 : 0);
                bool ok = ((unsigned)j < NN) && ((unsigned)(j - i + 128) <= 256u);
                float pv = ok ? __expf(s[e]) : 0.f;
                p[e] = pv;
                if (e & 2) lsum1 += pv; else lsum0 += pv;
            }
            uint32_t pah[4];
            #pragma unroll
            for (int q2 = 0; q2 < 4; q2++)
                pah[q2] = packh2(p[2 * q2], p[2 * q2 + 1]);

            const int vrow = 16 * g + vroff;
            #pragma unroll
            for (int nj = 0; nj < 4; nj++) {
                uint32_t off = swz(vrow, 2 * nj + vchoff);
                uint32_t vb[4];
                ldsm4t(vb, smb + SVH + off);
                mma16816(oacc[2*nj],   pah, vb[0], vb[1]);
                mma16816(oacc[2*nj+1], pah, vb[2], vb[3]);
            }
        }
        __syncthreads();
    }

    lsum0 += __shfl_xor_sync(0xffffffffu, lsum0, 1);
    lsum0 += __shfl_xor_sync(0xffffffffu, lsum0, 2);
    lsum1 += __shfl_xor_sync(0xffffffffu, lsum1, 1);
    lsum1 += __shfl_xor_sync(0xffffffffu, lsum1, 2);
    const float inv0 = 1.f / lsum0, inv1 = 1.f / lsum1;

    const size_t r0 = (size_t)(b * NN + q0 + 16 * w + (lane >> 2));
    const int colb = hcol + 2 * (lane & 3);
    #pragma unroll
    for (int t = 0; t < 8; t++) {
        int col = colb + 8 * t;
        *(uint32_t*)&oah[r0 * INNER + col] =
            packh2(oacc[t][0] * inv0, oacc[t][1] * inv0);
        *(uint32_t*)&oah[(r0 + 8) * INNER + col] =
            packh2(oacc[t][2] * inv1, oacc[t][3] * inv1);
    }
}

// ---------------- launch ------------------------------------------------------
extern "C" void kernel_launch(void* const* d_in, const int* in_sizes, int n_in,
                              void* d_out, int out_size)
{
    const float* x     = (const float*)d_in[0];
    const float* freqs = (const float*)d_in[2];
    const float* Wq    = (const float*)d_in[3];
    const float* bq    = (const float*)d_in[4];
    const float* Wk    = (const float*)d_in[5];
    const float* bk    = (const float*)d_in[6];
    const float* Wv    = (const float*)d_in[7];
    const float* bv    = (const float*)d_in[8];
    const float* Wo    = (const float*)d_in[9];
    const float* bo    = (const float*)d_in[10];
    float* out = (float*)d_out;

    float* dmy;
    __half *xh, *ah, *whi, *qh, *kh, *vh;
    cudaGetSymbolAddress((void**)&dmy, g_dummy);
    cudaGetSymbolAddress((void**)&xh,  g_xh);
    cudaGetSymbolAddress((void**)&ah,  g_ah);
    cudaGetSymbolAddress((void**)&whi, g_whi);
    cudaGetSymbolAddress((void**)&qh,  g_qh);
    cudaGetSymbolAddress((void**)&kh,  g_kh);
    cudaGetSymbolAddress((void**)&vh,  g_vh);

    cudaFuncSetAttribute(gemm_f16,
                         cudaFuncAttributeMaxDynamicSharedMemorySize, GSMEM);
    cudaFuncSetAttribute(attn_mma,
                         cudaFuncAttributeMaxDynamicSharedMemorySize, ASMEM);

    const size_t WSZ = (size_t)KDIM * KDIM;

    convert_all<<<(8 * N4W) / 256, 256>>>(x, Wq, Wk, Wv, Wo, whi, xh);  // #1
    dummy_k<<<1, 32>>>(dmy);                                            // #2
    dummy_k<<<1, 32>>>(dmy);                                            // #3

    // fused QKV projection (#4): fp16 row-major epilogue, Q scaled by 1/8
    dim3 gGridQKV(24, ROWS / 128);
    gemm_f16<<<gGridQKV, 256, GSMEM>>>(xh, whi, bq, bk, bv,
                                       nullptr, qh, kh, vh, 1);

    // windowed attention with fused head-0 RoPE
    dim3 attGrid(NN / 128, BB * HH);
    attn_mma<<<attGrid, 256, ASMEM>>>(qh, kh, vh, freqs, ah);

    // output projection: fp32 epilogue to harness buffer
    dim3 gGridO(8, ROWS / 128);
    gemm_f16<<<gGridO, 256, GSMEM>>>(ah, whi + 3*WSZ, bo, bo, bo,
                                     out, nullptr, nullptr, nullptr, 0);
}